// round 7
// baseline (speedup 1.0000x reference)
#include <cuda_runtime.h>
#include <math.h>
#include <cstdint>

#define NB 4
#define NS 2048
#define ND 1024
#define NH 16
#define NKV 4
#define NHD 64
#define MTOT (NB * NS)   // 8192

// ---------------- scratch (static device globals; no allocation) -------------
__device__ float g_q[(size_t)MTOT * ND];
__device__ float g_k[(size_t)MTOT * NKV * NHD];
__device__ float g_v[(size_t)MTOT * NKV * NHD];
__device__ float g_o[(size_t)MTOT * ND];
__device__ float g_xt[(size_t)MTOT * ND];          // tf32-rounded x
__device__ float g_wqt[(size_t)ND * ND];
__device__ float g_wkt[(size_t)ND * 256];
__device__ float g_wvt[(size_t)ND * 256];
__device__ float g_wot[(size_t)ND * ND];

// ---------------- helpers -----------------------------------------------------
__device__ __forceinline__ uint32_t f2tf(float f) {
    uint32_t r;
    asm("cvt.rna.tf32.f32 %0, %1;" : "=r"(r) : "f"(f));
    return r;
}
__device__ __forceinline__ float ex2(float x) {
    float y;
    asm("ex2.approx.f32 %0, %1;" : "=f"(y) : "f"(x));
    return y;
}
__device__ __forceinline__ uint32_t smem_u32(const void* p) {
    uint32_t a;
    asm("{ .reg .u64 t; cvta.to.shared.u64 t, %1; cvt.u32.u64 %0, t; }" : "=r"(a) : "l"(p));
    return a;
}
__device__ __forceinline__ void ldmx4(uint32_t* r, uint32_t addr) {
    asm volatile("ldmatrix.sync.aligned.m8n8.x4.shared.b16 {%0,%1,%2,%3}, [%4];"
                 : "=r"(r[0]), "=r"(r[1]), "=r"(r[2]), "=r"(r[3]) : "r"(addr));
}
__device__ __forceinline__ void ldmx2(uint32_t* r, uint32_t addr) {
    asm volatile("ldmatrix.sync.aligned.m8n8.x2.shared.b16 {%0,%1}, [%2];"
                 : "=r"(r[0]), "=r"(r[1]) : "r"(addr));
}
__device__ __forceinline__ void cpa16(uint32_t dst, const void* src) {
    asm volatile("cp.async.ca.shared.global [%0], [%1], 16;" :: "r"(dst), "l"(src));
}
__device__ __forceinline__ void cpa_commit() {
    asm volatile("cp.async.commit_group;" ::: "memory");
}
__device__ __forceinline__ void cpa_wait0() {
    asm volatile("cp.async.wait_group 0;" ::: "memory");
}
__device__ __forceinline__ void cpa_wait1() {
    asm volatile("cp.async.wait_group 1;" ::: "memory");
}
__device__ __forceinline__ void mma8(float* c, const uint32_t* a, const uint32_t* b) {
    asm volatile(
        "mma.sync.aligned.m16n8k8.row.col.f32.tf32.tf32.f32 "
        "{%0,%1,%2,%3}, {%4,%5,%6,%7}, {%8,%9}, {%0,%1,%2,%3};"
        : "+f"(c[0]), "+f"(c[1]), "+f"(c[2]), "+f"(c[3])
        : "r"(a[0]), "r"(a[1]), "r"(a[2]), "r"(a[3]), "r"(b[0]), "r"(b[1]));
}

// ---------------- pre-round to tf32 bits -------------------------------------
__global__ __launch_bounds__(256) void round_tf(const float* __restrict__ src,
                                                float* __restrict__ dst, int n4) {
    int i = blockIdx.x * blockDim.x + threadIdx.x;
    if (i >= n4) return;
    float4 v = ((const float4*)src)[i];
    uint4 r = make_uint4(f2tf(v.x), f2tf(v.y), f2tf(v.z), f2tf(v.w));
    ((uint4*)dst)[i] = r;
}

// ---------------- tf32 GEMM: cp.async 3-stage, no in-loop cvt ----------------
// Inputs pre-rounded to tf32 bits. 128 thr (4 warps 2x2), tile 128x128x16,
// warp tile 64x64.
#define AP 20
#define WPX 136
#define ABUF (128 * AP)       // 2560 words
#define WBUF (16 * WPX)       // 2176 words
#define GSW (3 * (ABUF + WBUF))   // 14208 words = 56832 B

template <bool RND>
__device__ __forceinline__ void tgemm_body(const float* __restrict__ A,
                                           const float* __restrict__ W,
                                           float* __restrict__ C,
                                           int M, int N, int K, uint32_t* sm) {
    const int tid = threadIdx.x, wid = tid >> 5, lane = tid & 31;
    const int g = lane >> 2, tg = lane & 3;
    const int bm = blockIdx.y, bn = blockIdx.x;
    const int wm = wid >> 1, wn = wid & 1;
    const int arow_l = (lane & 7) + ((lane >> 3) & 1) * 8;
    const int kcol_l = (lane >> 4) * 4;

    const uint32_t smb = smem_u32(sm);
    const uint32_t ws0 = 3 * ABUF;   // word offset of W buffers

    const int row_a = tid >> 2, ca = (tid & 3) * 4;
    const int kw = tid >> 5, nw = (tid & 31) * 4;
    const float* Ap = A + (size_t)(bm * 128 + row_a) * K + ca;
    const float* Wp = W + (size_t)kw * N + bn * 128 + nw;

    const int nk = K / 16;

    auto load_tile = [&](int kt, int buf) {
        const uint32_t ab = smb + (uint32_t)(buf * ABUF) * 4;
        const uint32_t wb = smb + (uint32_t)(ws0 + buf * WBUF) * 4;
#pragma unroll
        for (int r = 0; r < 4; r++) {
            cpa16(ab + (uint32_t)((r * 32 + row_a) * AP + ca) * 4,
                  Ap + kt * 16 + (size_t)r * 32 * K);
            cpa16(wb + (uint32_t)((r * 4 + kw) * WPX + nw) * 4,
                  Wp + (size_t)(kt * 16 + r * 4) * N);
        }
        cpa_commit();
    };

    float acc[4][8][4];
#pragma unroll
    for (int i = 0; i < 4; i++)
#pragma unroll
        for (int j = 0; j < 8; j++)
#pragma unroll
            for (int r = 0; r < 4; r++) acc[i][j][r] = 0.f;

    load_tile(0, 0);
    load_tile(1, 1);

    int cur = 0;
    for (int kt = 0; kt < nk; kt++) {
        if (kt + 1 < nk) cpa_wait1(); else cpa_wait0();
        __syncthreads();
        int pre = cur + 2; if (pre >= 3) pre -= 3;
        if (kt + 2 < nk) load_tile(kt + 2, pre);

        const uint32_t ab = smb + (uint32_t)(cur * ABUF) * 4;
        const uint32_t wb_w = ws0 + cur * WBUF;
#pragma unroll
        for (int ks = 0; ks < 2; ks++) {
            const int k0 = ks * 8;
            uint32_t a[4][4];
#pragma unroll
            for (int mt = 0; mt < 4; mt++)
                ldmx4(a[mt], ab + (uint32_t)((wm * 64 + mt * 16 + arow_l) * AP + k0 + kcol_l) * 4);
#pragma unroll
            for (int nt = 0; nt < 8; nt++) {
                uint32_t b[2];
                int cn = wn * 64 + nt * 8 + g;
                b[0] = sm[wb_w + (k0 + tg) * WPX + cn];
                b[1] = sm[wb_w + (k0 + tg + 4) * WPX + cn];
                mma8(acc[0][nt], a[0], b);
                mma8(acc[1][nt], a[1], b);
                mma8(acc[2][nt], a[2], b);
                mma8(acc[3][nt], a[3], b);
            }
        }
        if (++cur == 3) cur = 0;
    }

#pragma unroll
    for (int mt = 0; mt < 4; mt++)
#pragma unroll
        for (int nt = 0; nt < 8; nt++) {
            int row = bm * 128 + wm * 64 + mt * 16 + g;
            int col = bn * 128 + wn * 64 + nt * 8 + 2 * tg;
            if (RND) {
                *(uint2*)(C + (size_t)row * N + col) =
                    make_uint2(f2tf(acc[mt][nt][0]), f2tf(acc[mt][nt][1]));
                *(uint2*)(C + (size_t)(row + 8) * N + col) =
                    make_uint2(f2tf(acc[mt][nt][2]), f2tf(acc[mt][nt][3]));
            } else {
                *(float2*)(C + (size_t)row * N + col) =
                    make_float2(acc[mt][nt][0], acc[mt][nt][1]);
                *(float2*)(C + (size_t)(row + 8) * N + col) =
                    make_float2(acc[mt][nt][2], acc[mt][nt][3]);
            }
        }
}

template <bool RND>
__global__ void __launch_bounds__(128, 3) tgemm(const float* __restrict__ A,
                                                const float* __restrict__ W,
                                                float* __restrict__ C,
                                                int M, int N, int K) {
    extern __shared__ uint32_t smg[];
    tgemm_body<RND>(A, W, C, M, N, K, smg);
}

__global__ void __launch_bounds__(128, 3) tgemm_dual(const float* __restrict__ A,
                                                     const float* __restrict__ W0,
                                                     const float* __restrict__ W1,
                                                     float* __restrict__ C0,
                                                     float* __restrict__ C1,
                                                     int M, int N, int K) {
    extern __shared__ uint32_t smg[];
    const float* W = blockIdx.z ? W1 : W0;
    float* C = blockIdx.z ? C1 : C0;
    tgemm_body<true>(A, W, C, M, N, K, smg);
}

// ---------------- Flash attention: pre-rounded inputs, cp.async, 3 blk/SM ----
#define QP 68
#define VP 72
#define SM_P 0
#define SM_K (128 * QP)                 // 8704
#define SM_V (SM_K + 64 * QP)           // + 4352
#define SM_TOT (SM_V + 64 * VP)         // 17664 words = 70656 B

__global__ void __launch_bounds__(128, 3) attn_mma() {
    extern __shared__ uint32_t sm4[];
    const uint32_t smb = smem_u32(sm4);
    uint32_t* Ps = sm4 + SM_P;
    uint32_t* Vs = sm4 + SM_V;

    const int qb = blockIdx.x, h = blockIdx.y, b = blockIdx.z;
    const int kvh = h >> 2;
    const int tid = threadIdx.x, w = tid >> 5, lane = tid & 31;
    const int g = lane >> 2, tg = lane & 3;
    const int arow_l = (lane & 7) + ((lane >> 3) & 1) * 8;
    const int kcol_l = (lane >> 4) * 4;
    const int brow_l = lane & 7, bk_l = ((lane >> 3) & 1) * 4;

    const float LOG2E = 1.4426950408889634f;
    const float sc2 = 0.125f * LOG2E;
    const float slope2 = ex2(-0.5f * (float)(h + 1)) * LOG2E;

    const int lr = tid >> 4;            // loader row within 8-row group
    const int lc = (tid & 15) * 4;      // loader col (floats)

    const float* kbase = g_k + (size_t)(b * NS) * 256 + kvh * NHD;
    const float* vbase = g_v + (size_t)(b * NS) * 256 + kvh * NHD;

    // stage Q tile [128 x 64] (pre-rounded bits) into P region via cp.async
    {
        const float* qbase = g_q + (size_t)(b * NS + qb * 128) * ND + h * NHD;
#pragma unroll
        for (int rep = 0; rep < 16; rep++) {
            int r = rep * 8 + lr;
            cpa16(smb + (uint32_t)(SM_P + r * QP + lc) * 4, qbase + (size_t)r * ND + lc);
        }
        cpa_commit();
        cpa_wait0();
    }
    __syncthreads();

    // Q fragments -> registers (warp-private rows)
    uint32_t qf[8][2][4];
#pragma unroll
    for (int ks = 0; ks < 8; ks++)
#pragma unroll
        for (int mt = 0; mt < 2; mt++)
            ldmx4(qf[ks][mt], smb + (uint32_t)(SM_P +
                    (w * 32 + mt * 16 + arow_l) * QP + ks * 8 + kcol_l) * 4);

    float m[4], l[4], O[2][8][4];
#pragma unroll
    for (int i = 0; i < 4; i++) { m[i] = -INFINITY; l[i] = 0.f; }
#pragma unroll
    for (int mt = 0; mt < 2; mt++)
#pragma unroll
        for (int nt = 0; nt < 8; nt++)
#pragma unroll
            for (int r = 0; r < 4; r++) O[mt][nt][r] = 0.f;

    float rowi[4];
#pragma unroll
    for (int mt = 0; mt < 2; mt++) {
        rowi[2 * mt]     = (float)(qb * 128 + w * 32 + mt * 16 + g);
        rowi[2 * mt + 1] = rowi[2 * mt] + 8.f;
    }

    const int NCH = NS / 64;
    for (int kt = 0; kt < NCH; kt++) {
        __syncthreads();  // all warps done reading K/V of previous chunk
        const float* kp = kbase + (size_t)kt * 64 * 256;
        const float* vp = vbase + (size_t)kt * 64 * 256;
#pragma unroll
        for (int rep = 0; rep < 8; rep++) {
            int r = rep * 8 + lr;
            cpa16(smb + (uint32_t)(SM_K + r * QP + lc) * 4, kp + (size_t)r * 256 + lc);
            cpa16(smb + (uint32_t)(SM_V + r * VP + lc) * 4, vp + (size_t)r * 256 + lc);
        }
        cpa_commit();
        cpa_wait0();
        __syncthreads();  // K,V visible to all

        // per-mt: S = Q K^T, softmax, P write
#pragma unroll
        for (int mt = 0; mt < 2; mt++) {
            float S[8][4];
#pragma unroll
            for (int nt = 0; nt < 8; nt++)
#pragma unroll
                for (int r = 0; r < 4; r++) S[nt][r] = 0.f;

#pragma unroll
            for (int ks = 0; ks < 8; ks++) {
#pragma unroll
                for (int nt = 0; nt < 8; nt++) {
                    uint32_t bb[2];
                    ldmx2(bb, smb + (uint32_t)(SM_K +
                            (nt * 8 + brow_l) * QP + ks * 8 + bk_l) * 4);
                    mma8(S[nt], qf[ks][mt], bb);
                }
            }

            float mx0 = -INFINITY, mx1 = -INFINITY;
#pragma unroll
            for (int nt = 0; nt < 8; nt++) {
                float j0 = (float)(kt * 64 + nt * 8 + 2 * tg);
                S[nt][0] = S[nt][0] * sc2 + slope2 * (j0 - rowi[2 * mt]);
                S[nt][1] = S[nt][1] * sc2 + slope2 * (j0 + 1.f - rowi[2 * mt]);
                S[nt][2] = S[nt][2] * sc2 + slope2 * (j0 - rowi[2 * mt + 1]);
                S[nt][3] = S[nt][3] * sc2 + slope2 * (j0 + 1.f - rowi[2 * mt + 1]);
                mx0 = fmaxf(mx0, fmaxf(S[nt][0], S[nt][1]));
                mx1 = fmaxf(mx1, fmaxf(S[nt][2], S[nt][3]));
            }
            mx0 = fmaxf(mx0, __shfl_xor_sync(0xffffffffu, mx0, 1));
            mx0 = fmaxf(mx0, __shfl_xor_sync(0xffffffffu, mx0, 2));
            mx1 = fmaxf(mx1, __shfl_xor_sync(0xffffffffu, mx1, 1));
            mx1 = fmaxf(mx1, __shfl_xor_sync(0xffffffffu, mx1, 2));

            float mn0 = fmaxf(m[2 * mt], mx0), mn1 = fmaxf(m[2 * mt + 1], mx1);
            float f0 = ex2(m[2 * mt] - mn0), f1 = ex2(m[2 * mt + 1] - mn1);
            m[2 * mt] = mn0; m[2 * mt + 1] = mn1;

            float rs0 = 0.f, rs1 = 0.f;
#pragma unroll
            for (int nt = 0; nt < 8; nt++) {
                S[nt][0] = ex2(S[nt][0] - mn0);
                S[nt][1] = ex2(S[nt][1] - mn0);
                S[nt][2] = ex2(S[nt][2] - mn1);
                S[nt][3] = ex2(S[nt][3] - mn1);
                rs0 += S[nt][0] + S[nt][1];
                rs1 += S[nt][2] + S[nt][3];
            }
            rs0 += __shfl_xor_sync(0xffffffffu, rs0, 1);
            rs0 += __shfl_xor_sync(0xffffffffu, rs0, 2);
            rs1 += __shfl_xor_sync(0xffffffffu, rs1, 1);
            rs1 += __shfl_xor_sync(0xffffffffu, rs1, 2);
            l[2 * mt] = l[2 * mt] * f0 + rs0;
            l[2 * mt + 1] = l[2 * mt + 1] * f1 + rs1;

#pragma unroll
            for (int nt = 0; nt < 8; nt++) {
                O[mt][nt][0] *= f0; O[mt][nt][1] *= f0;
                O[mt][nt][2] *= f1; O[mt][nt][3] *= f1;
            }

            int rL = w * 32 + mt * 16 + g, rH = rL + 8;
#pragma unroll
            for (int nt = 0; nt < 8; nt++) {
                *(uint2*)&Ps[rL * QP + nt * 8 + 2 * tg] =
                    make_uint2(f2tf(S[nt][0]), f2tf(S[nt][1]));
                *(uint2*)&Ps[rH * QP + nt * 8 + 2 * tg] =
                    make_uint2(f2tf(S[nt][2]), f2tf(S[nt][3]));
            }
        }
        __syncwarp();  // P rows are warp-private

        // O += P @ V
#pragma unroll
        for (int ks = 0; ks < 8; ks++) {
            const int k0 = ks * 8;
            uint32_t a[2][4];
#pragma unroll
            for (int mt = 0; mt < 2; mt++)
                ldmx4(a[mt], smb + (uint32_t)(SM_P +
                        (w * 32 + mt * 16 + arow_l) * QP + k0 + kcol_l) * 4);
#pragma unroll
            for (int nt = 0; nt < 8; nt++) {
                uint32_t bb[2];
                bb[0] = Vs[(k0 + tg) * VP + nt * 8 + g];
                bb[1] = Vs[(k0 + tg + 4) * VP + nt * 8 + g];
                mma8(O[0][nt], a[0], bb);
                mma8(O[1][nt], a[1], bb);
            }
        }
    }

    // epilogue: normalize, round to tf32 bits (feeds Wo GEMM), store
#pragma unroll
    for (int mt = 0; mt < 2; mt++) {
        float inv0 = 1.f / l[2 * mt], inv1 = 1.f / l[2 * mt + 1];
        int rL = qb * 128 + w * 32 + mt * 16 + g;
        float* ob = g_o + (size_t)(b * NS + rL) * ND + h * NHD;
#pragma unroll
        for (int nt = 0; nt < 8; nt++) {
            *(uint2*)(ob + nt * 8 + 2 * tg) =
                make_uint2(f2tf(O[mt][nt][0] * inv0), f2tf(O[mt][nt][1] * inv0));
            *(uint2*)(ob + (size_t)8 * ND + nt * 8 + 2 * tg) =
                make_uint2(f2tf(O[mt][nt][2] * inv1), f2tf(O[mt][nt][3] * inv1));
        }
    }
}

// ---------------- launch ------------------------------------------------------
extern "C" void kernel_launch(void* const* d_in, const int* in_sizes, int n_in,
                              void* d_out, int out_size) {
    const float* x  = (const float*)d_in[0];
    const float* Wq = (const float*)d_in[1];
    const float* Wk = (const float*)d_in[2];
    const float* Wv = (const float*)d_in[3];
    const float* Wo = (const float*)d_in[4];
    float* out = (float*)d_out;

    float *q, *k, *v, *o, *xt, *wqt, *wkt, *wvt, *wot;
    cudaGetSymbolAddress((void**)&q, g_q);
    cudaGetSymbolAddress((void**)&k, g_k);
    cudaGetSymbolAddress((void**)&v, g_v);
    cudaGetSymbolAddress((void**)&o, g_o);
    cudaGetSymbolAddress((void**)&xt, g_xt);
    cudaGetSymbolAddress((void**)&wqt, g_wqt);
    cudaGetSymbolAddress((void**)&wkt, g_wkt);
    cudaGetSymbolAddress((void**)&wvt, g_wvt);
    cudaGetSymbolAddress((void**)&wot, g_wot);

    const int gsmem = GSW * sizeof(uint32_t);          // 56832 B
    const int smem_attn = SM_TOT * sizeof(uint32_t);   // 70656 B
    cudaFuncSetAttribute(tgemm<true>, cudaFuncAttributeMaxDynamicSharedMemorySize, gsmem);
    cudaFuncSetAttribute(tgemm<false>, cudaFuncAttributeMaxDynamicSharedMemorySize, gsmem);
    cudaFuncSetAttribute(tgemm_dual, cudaFuncAttributeMaxDynamicSharedMemorySize, gsmem);
    cudaFuncSetAttribute(attn_mma, cudaFuncAttributeMaxDynamicSharedMemorySize, smem_attn);

    // pre-round inputs to tf32 bits
    round_tf<<<(MTOT * ND / 4 + 255) / 256, 256>>>(x, xt, MTOT * ND / 4);
    round_tf<<<(ND * ND / 4 + 255) / 256, 256>>>(Wq, wqt, ND * ND / 4);
    round_tf<<<(ND * 256 / 4 + 255) / 256, 256>>>(Wk, wkt, ND * 256 / 4);
    round_tf<<<(ND * 256 / 4 + 255) / 256, 256>>>(Wv, wvt, ND * 256 / 4);
    round_tf<<<(ND * ND / 4 + 255) / 256, 256>>>(Wo, wot, ND * ND / 4);

    // projections (outputs rounded to tf32 bits)
    tgemm<true><<<dim3(ND / 128, MTOT / 128), 128, gsmem>>>(xt, wqt, q, MTOT, ND, ND);
    tgemm_dual<<<dim3(256 / 128, MTOT / 128, 2), 128, gsmem>>>(xt, wkt, wvt, k, v, MTOT, 256, ND);

    attn_mma<<<dim3(NS / 128, NH, NB), 128, smem_attn>>>();

    // output projection (exact fp32 store)
    tgemm<false><<<dim3(ND / 128, MTOT / 128), 128, gsmem>>>(o, wot, out, MTOT, ND, ND);
}

// round 8
// speedup vs baseline: 1.1247x; 1.1247x over previous
#include <cuda_runtime.h>
#include <math.h>
#include <cstdint>

#define NB 4
#define NS 2048
#define ND 1024
#define NH 16
#define NKV 4
#define NHD 64
#define MTOT (NB * NS)   // 8192

// ---------------- scratch (static device globals; no allocation) -------------
__device__ float g_q[(size_t)MTOT * ND];
__device__ float g_k[(size_t)MTOT * NKV * NHD];
__device__ float g_v[(size_t)MTOT * NKV * NHD];
__device__ float g_o[(size_t)MTOT * ND];
__device__ float g_xt[(size_t)MTOT * ND];
__device__ float g_wqt[(size_t)ND * ND];
__device__ float g_wkt[(size_t)ND * 256];
__device__ float g_wvt[(size_t)ND * 256];
__device__ float g_wot[(size_t)ND * ND];

// ---------------- helpers -----------------------------------------------------
__device__ __forceinline__ uint32_t f2tf(float f) {
    uint32_t r;
    asm("cvt.rna.tf32.f32 %0, %1;" : "=r"(r) : "f"(f));
    return r;
}
__device__ __forceinline__ float ex2(float x) {
    float y;
    asm("ex2.approx.f32 %0, %1;" : "=f"(y) : "f"(x));
    return y;
}
__device__ __forceinline__ uint32_t smem_u32(const void* p) {
    uint32_t a;
    asm("{ .reg .u64 t; cvta.to.shared.u64 t, %1; cvt.u32.u64 %0, t; }" : "=r"(a) : "l"(p));
    return a;
}
__device__ __forceinline__ void ldmx4(uint32_t* r, uint32_t addr) {
    asm volatile("ldmatrix.sync.aligned.m8n8.x4.shared.b16 {%0,%1,%2,%3}, [%4];"
                 : "=r"(r[0]), "=r"(r[1]), "=r"(r[2]), "=r"(r[3]) : "r"(addr));
}
__device__ __forceinline__ void ldmx2(uint32_t* r, uint32_t addr) {
    asm volatile("ldmatrix.sync.aligned.m8n8.x2.shared.b16 {%0,%1}, [%2];"
                 : "=r"(r[0]), "=r"(r[1]) : "r"(addr));
}
__device__ __forceinline__ void cpa16(uint32_t dst, const void* src) {
    asm volatile("cp.async.ca.shared.global [%0], [%1], 16;" :: "r"(dst), "l"(src));
}
__device__ __forceinline__ void cpa_commit() {
    asm volatile("cp.async.commit_group;" ::: "memory");
}
__device__ __forceinline__ void cpa_wait0() {
    asm volatile("cp.async.wait_group 0;" ::: "memory");
}
__device__ __forceinline__ void cpa_wait1() {
    asm volatile("cp.async.wait_group 1;" ::: "memory");
}
__device__ __forceinline__ void mma8(float* c, const uint32_t* a, const uint32_t* b) {
    asm volatile(
        "mma.sync.aligned.m16n8k8.row.col.f32.tf32.tf32.f32 "
        "{%0,%1,%2,%3}, {%4,%5,%6,%7}, {%8,%9}, {%0,%1,%2,%3};"
        : "+f"(c[0]), "+f"(c[1]), "+f"(c[2]), "+f"(c[3])
        : "r"(a[0]), "r"(a[1]), "r"(a[2]), "r"(a[3]), "r"(b[0]), "r"(b[1]));
}

// ---------------- single merged pre-round kernel ------------------------------
#define RN0 (MTOT * ND / 4)                    // x      2097152
#define RN1 (RN0 + ND * ND / 4)                // +wq     262144
#define RN2 (RN1 + ND * 256 / 4)               // +wk      65536
#define RN3 (RN2 + ND * 256 / 4)               // +wv      65536
#define RN4 (RN3 + ND * ND / 4)                // +wo     262144

__global__ __launch_bounds__(256) void round_all(
    const float* __restrict__ x,  float* __restrict__ xt,
    const float* __restrict__ wq, float* __restrict__ wqt,
    const float* __restrict__ wk, float* __restrict__ wkt,
    const float* __restrict__ wv, float* __restrict__ wvt,
    const float* __restrict__ wo, float* __restrict__ wot) {
    int i = blockIdx.x * 256 + threadIdx.x;
    const float* s; float* d; int j;
    if (i < RN0)      { s = x;  d = xt;  j = i; }
    else if (i < RN1) { s = wq; d = wqt; j = i - RN0; }
    else if (i < RN2) { s = wk; d = wkt; j = i - RN1; }
    else if (i < RN3) { s = wv; d = wvt; j = i - RN2; }
    else if (i < RN4) { s = wo; d = wot; j = i - RN3; }
    else return;
    float4 v = ((const float4*)s)[j];
    ((uint4*)d)[j] = make_uint4(f2tf(v.x), f2tf(v.y), f2tf(v.z), f2tf(v.w));
}

// ---------------- tf32 GEMM: cp.async 3-stage (unchanged from R7) ------------
#define AP 20
#define WPX 136
#define ABUF (128 * AP)
#define WBUF (16 * WPX)
#define GSW (3 * (ABUF + WBUF))   // 14208 words = 56832 B

template <bool RND>
__device__ __forceinline__ void tgemm_body(const float* __restrict__ A,
                                           const float* __restrict__ W,
                                           float* __restrict__ C,
                                           int M, int N, int K, uint32_t* sm) {
    const int tid = threadIdx.x, wid = tid >> 5, lane = tid & 31;
    const int g = lane >> 2, tg = lane & 3;
    const int bm = blockIdx.y, bn = blockIdx.x;
    const int wm = wid >> 1, wn = wid & 1;
    const int arow_l = (lane & 7) + ((lane >> 3) & 1) * 8;
    const int kcol_l = (lane >> 4) * 4;

    const uint32_t smb = smem_u32(sm);
    const uint32_t ws0 = 3 * ABUF;

    const int row_a = tid >> 2, ca = (tid & 3) * 4;
    const int kw = tid >> 5, nw = (tid & 31) * 4;
    const float* Ap = A + (size_t)(bm * 128 + row_a) * K + ca;
    const float* Wp = W + (size_t)kw * N + bn * 128 + nw;

    const int nk = K / 16;

    auto load_tile = [&](int kt, int buf) {
        const uint32_t ab = smb + (uint32_t)(buf * ABUF) * 4;
        const uint32_t wb = smb + (uint32_t)(ws0 + buf * WBUF) * 4;
#pragma unroll
        for (int r = 0; r < 4; r++) {
            cpa16(ab + (uint32_t)((r * 32 + row_a) * AP + ca) * 4,
                  Ap + kt * 16 + (size_t)r * 32 * K);
            cpa16(wb + (uint32_t)((r * 4 + kw) * WPX + nw) * 4,
                  Wp + (size_t)(kt * 16 + r * 4) * N);
        }
        cpa_commit();
    };

    float acc[4][8][4];
#pragma unroll
    for (int i = 0; i < 4; i++)
#pragma unroll
        for (int j = 0; j < 8; j++)
#pragma unroll
            for (int r = 0; r < 4; r++) acc[i][j][r] = 0.f;

    load_tile(0, 0);
    load_tile(1, 1);

    int cur = 0;
    for (int kt = 0; kt < nk; kt++) {
        if (kt + 1 < nk) cpa_wait1(); else cpa_wait0();
        __syncthreads();
        int pre = cur + 2; if (pre >= 3) pre -= 3;
        if (kt + 2 < nk) load_tile(kt + 2, pre);

        const uint32_t ab = smb + (uint32_t)(cur * ABUF) * 4;
        const uint32_t wb_w = ws0 + cur * WBUF;
#pragma unroll
        for (int ks = 0; ks < 2; ks++) {
            const int k0 = ks * 8;
            uint32_t a[4][4];
#pragma unroll
            for (int mt = 0; mt < 4; mt++)
                ldmx4(a[mt], ab + (uint32_t)((wm * 64 + mt * 16 + arow_l) * AP + k0 + kcol_l) * 4);
#pragma unroll
            for (int nt = 0; nt < 8; nt++) {
                uint32_t b[2];
                int cn = wn * 64 + nt * 8 + g;
                b[0] = sm[wb_w + (k0 + tg) * WPX + cn];
                b[1] = sm[wb_w + (k0 + tg + 4) * WPX + cn];
                mma8(acc[0][nt], a[0], b);
                mma8(acc[1][nt], a[1], b);
                mma8(acc[2][nt], a[2], b);
                mma8(acc[3][nt], a[3], b);
            }
        }
        if (++cur == 3) cur = 0;
    }

#pragma unroll
    for (int mt = 0; mt < 4; mt++)
#pragma unroll
        for (int nt = 0; nt < 8; nt++) {
            int row = bm * 128 + wm * 64 + mt * 16 + g;
            int col = bn * 128 + wn * 64 + nt * 8 + 2 * tg;
            if (RND) {
                *(uint2*)(C + (size_t)row * N + col) =
                    make_uint2(f2tf(acc[mt][nt][0]), f2tf(acc[mt][nt][1]));
                *(uint2*)(C + (size_t)(row + 8) * N + col) =
                    make_uint2(f2tf(acc[mt][nt][2]), f2tf(acc[mt][nt][3]));
            } else {
                *(float2*)(C + (size_t)row * N + col) =
                    make_float2(acc[mt][nt][0], acc[mt][nt][1]);
                *(float2*)(C + (size_t)(row + 8) * N + col) =
                    make_float2(acc[mt][nt][2], acc[mt][nt][3]);
            }
        }
}

template <bool RND>
__global__ void __launch_bounds__(128, 3) tgemm(const float* __restrict__ A,
                                                const float* __restrict__ W,
                                                float* __restrict__ C,
                                                int M, int N, int K) {
    extern __shared__ uint32_t smg[];
    tgemm_body<RND>(A, W, C, M, N, K, smg);
}

__global__ void __launch_bounds__(128, 3) tgemm_dual(const float* __restrict__ A,
                                                     const float* __restrict__ W0,
                                                     const float* __restrict__ W1,
                                                     float* __restrict__ C0,
                                                     float* __restrict__ C1,
                                                     int M, int N, int K) {
    extern __shared__ uint32_t smg[];
    const float* W = blockIdx.z ? W1 : W0;
    float* C = blockIdx.z ? C1 : C0;
    tgemm_body<true>(A, W, C, M, N, K, smg);
}

// ---------------- Flash attention: K+V double-buffered cp.async --------------
// Block 128 thr (4 warps); q-tile 128 (32 rows/warp); kv chunks of 64.
// One __syncthreads per chunk; loads for kt+1 overlap compute of kt.
#define QP 68
#define VP 72
#define KBUF (64 * QP)                  // 4352 words
#define VBUF (64 * VP)                  // 4608 words
#define SM_P 0
#define SM_K (128 * QP)                 // 8704
#define SM_V (SM_K + 2 * KBUF)          // 8704 + 8704
#define SM_TOT (SM_V + 2 * VBUF)        // 26624 words = 106496 B

__global__ void __launch_bounds__(128, 2) attn_mma() {
    extern __shared__ uint32_t sm4[];
    const uint32_t smb = smem_u32(sm4);
    uint32_t* Ps = sm4 + SM_P;

    const int qb = blockIdx.x, h = blockIdx.y, b = blockIdx.z;
    const int kvh = h >> 2;
    const int tid = threadIdx.x, w = tid >> 5, lane = tid & 31;
    const int g = lane >> 2, tg = lane & 3;
    const int arow_l = (lane & 7) + ((lane >> 3) & 1) * 8;
    const int kcol_l = (lane >> 4) * 4;
    const int brow_l = lane & 7, bk_l = ((lane >> 3) & 1) * 4;

    const float LOG2E = 1.4426950408889634f;
    const float sc2 = 0.125f * LOG2E;
    const float slope2 = ex2(-0.5f * (float)(h + 1)) * LOG2E;

    const int lr = tid >> 4;            // loader row in 8-row group
    const int lc = (tid & 15) * 4;      // loader col (floats)

    const float* kbase = g_k + (size_t)(b * NS) * 256 + kvh * NHD;
    const float* vbase = g_v + (size_t)(b * NS) * 256 + kvh * NHD;

    auto issue_kv = [&](int kt, int buf) {
        const float* kp = kbase + (size_t)kt * 64 * 256;
        const float* vp = vbase + (size_t)kt * 64 * 256;
        const uint32_t kd = smb + (uint32_t)(SM_K + buf * KBUF) * 4;
        const uint32_t vd = smb + (uint32_t)(SM_V + buf * VBUF) * 4;
#pragma unroll
        for (int rep = 0; rep < 8; rep++) {
            int r = rep * 8 + lr;
            cpa16(kd + (uint32_t)(r * QP + lc) * 4, kp + (size_t)r * 256 + lc);
            cpa16(vd + (uint32_t)(r * VP + lc) * 4, vp + (size_t)r * 256 + lc);
        }
        cpa_commit();
    };

    // prologue: K/V chunk 0 + Q tile in flight together
    issue_kv(0, 0);
    {
        const float* qbase = g_q + (size_t)(b * NS + qb * 128) * ND + h * NHD;
#pragma unroll
        for (int rep = 0; rep < 16; rep++) {
            int r = rep * 8 + lr;
            cpa16(smb + (uint32_t)(SM_P + r * QP + lc) * 4, qbase + (size_t)r * ND + lc);
        }
        cpa_commit();
    }
    cpa_wait0();
    __syncthreads();

    // Q fragments -> registers (warp-private rows)
    uint32_t qf[8][2][4];
#pragma unroll
    for (int ks = 0; ks < 8; ks++)
#pragma unroll
        for (int mt = 0; mt < 2; mt++)
            ldmx4(qf[ks][mt], smb + (uint32_t)(SM_P +
                    (w * 32 + mt * 16 + arow_l) * QP + ks * 8 + kcol_l) * 4);

    float m[4], l[4], O[2][8][4];
#pragma unroll
    for (int i = 0; i < 4; i++) { m[i] = -INFINITY; l[i] = 0.f; }
#pragma unroll
    for (int mt = 0; mt < 2; mt++)
#pragma unroll
        for (int nt = 0; nt < 8; nt++)
#pragma unroll
            for (int r = 0; r < 4; r++) O[mt][nt][r] = 0.f;

    float rowi[4];
#pragma unroll
    for (int mt = 0; mt < 2; mt++) {
        rowi[2 * mt]     = (float)(qb * 128 + w * 32 + mt * 16 + g);
        rowi[2 * mt + 1] = rowi[2 * mt] + 8.f;
    }

    const int NCH = NS / 64;
    for (int kt = 0; kt < NCH; kt++) {
        const int kb = kt & 1;
        if (kt + 1 < NCH) issue_kv(kt + 1, kb ^ 1);

        const uint32_t kcur = SM_K + kb * KBUF;
        const uint32_t vcur_w = SM_V + kb * VBUF;

        // per-mt: S = Q K^T, softmax, P write
#pragma unroll
        for (int mt = 0; mt < 2; mt++) {
            float S[8][4];
#pragma unroll
            for (int nt = 0; nt < 8; nt++)
#pragma unroll
                for (int r = 0; r < 4; r++) S[nt][r] = 0.f;

#pragma unroll
            for (int ks = 0; ks < 8; ks++) {
#pragma unroll
                for (int nt = 0; nt < 8; nt++) {
                    uint32_t bb[2];
                    ldmx2(bb, smb + (uint32_t)(kcur +
                            (nt * 8 + brow_l) * QP + ks * 8 + bk_l) * 4);
                    mma8(S[nt], qf[ks][mt], bb);
                }
            }

            float mx0 = -INFINITY, mx1 = -INFINITY;
#pragma unroll
            for (int nt = 0; nt < 8; nt++) {
                float j0 = (float)(kt * 64 + nt * 8 + 2 * tg);
                S[nt][0] = S[nt][0] * sc2 + slope2 * (j0 - rowi[2 * mt]);
                S[nt][1] = S[nt][1] * sc2 + slope2 * (j0 + 1.f - rowi[2 * mt]);
                S[nt][2] = S[nt][2] * sc2 + slope2 * (j0 - rowi[2 * mt + 1]);
                S[nt][3] = S[nt][3] * sc2 + slope2 * (j0 + 1.f - rowi[2 * mt + 1]);
                mx0 = fmaxf(mx0, fmaxf(S[nt][0], S[nt][1]));
                mx1 = fmaxf(mx1, fmaxf(S[nt][2], S[nt][3]));
            }
            mx0 = fmaxf(mx0, __shfl_xor_sync(0xffffffffu, mx0, 1));
            mx0 = fmaxf(mx0, __shfl_xor_sync(0xffffffffu, mx0, 2));
            mx1 = fmaxf(mx1, __shfl_xor_sync(0xffffffffu, mx1, 1));
            mx1 = fmaxf(mx1, __shfl_xor_sync(0xffffffffu, mx1, 2));

            float mn0 = fmaxf(m[2 * mt], mx0), mn1 = fmaxf(m[2 * mt + 1], mx1);
            float f0 = ex2(m[2 * mt] - mn0), f1 = ex2(m[2 * mt + 1] - mn1);
            m[2 * mt] = mn0; m[2 * mt + 1] = mn1;

            float rs0 = 0.f, rs1 = 0.f;
#pragma unroll
            for (int nt = 0; nt < 8; nt++) {
                S[nt][0] = ex2(S[nt][0] - mn0);
                S[nt][1] = ex2(S[nt][1] - mn0);
                S[nt][2] = ex2(S[nt][2] - mn1);
                S[nt][3] = ex2(S[nt][3] - mn1);
                rs0 += S[nt][0] + S[nt][1];
                rs1 += S[nt][2] + S[nt][3];
            }
            rs0 += __shfl_xor_sync(0xffffffffu, rs0, 1);
            rs0 += __shfl_xor_sync(0xffffffffu, rs0, 2);
            rs1 += __shfl_xor_sync(0xffffffffu, rs1, 1);
            rs1 += __shfl_xor_sync(0xffffffffu, rs1, 2);
            l[2 * mt] = l[2 * mt] * f0 + rs0;
            l[2 * mt + 1] = l[2 * mt + 1] * f1 + rs1;

#pragma unroll
            for (int nt = 0; nt < 8; nt++) {
                O[mt][nt][0] *= f0; O[mt][nt][1] *= f0;
                O[mt][nt][2] *= f1; O[mt][nt][3] *= f1;
            }

            int rL = w * 32 + mt * 16 + g, rH = rL + 8;
#pragma unroll
            for (int nt = 0; nt < 8; nt++) {
                *(uint2*)&Ps[rL * QP + nt * 8 + 2 * tg] =
                    make_uint2(f2tf(S[nt][0]), f2tf(S[nt][1]));
                *(uint2*)&Ps[rH * QP + nt * 8 + 2 * tg] =
                    make_uint2(f2tf(S[nt][2]), f2tf(S[nt][3]));
            }
        }
        __syncwarp();  // P rows warp-private

        // O += P @ V
#pragma unroll
        for (int ks = 0; ks < 8; ks++) {
            const int k0 = ks * 8;
            uint32_t a[2][4];
#pragma unroll
            for (int mt = 0; mt < 2; mt++)
                ldmx4(a[mt], smb + (uint32_t)(SM_P +
                        (w * 32 + mt * 16 + arow_l) * QP + k0 + kcol_l) * 4);
#pragma unroll
            for (int nt = 0; nt < 8; nt++) {
                uint32_t bb[2];
                bb[0] = sm4[vcur_w + (k0 + tg) * VP + nt * 8 + g];
                bb[1] = sm4[vcur_w + (k0 + tg + 4) * VP + nt * 8 + g];
                mma8(O[0][nt], a[0], bb);
                mma8(O[1][nt], a[1], bb);
            }
        }

        if (kt + 1 < NCH) {
            cpa_wait0();       // K/V(kt+1) landed (overlapped with compute above)
            __syncthreads();   // all warps done with current buffers + see new data
        }
    }

    // epilogue: normalize, round to tf32 bits (feeds Wo GEMM), store
#pragma unroll
    for (int mt = 0; mt < 2; mt++) {
        float inv0 = 1.f / l[2 * mt], inv1 = 1.f / l[2 * mt + 1];
        int rL = qb * 128 + w * 32 + mt * 16 + g;
        float* ob = g_o + (size_t)(b * NS + rL) * ND + h * NHD;
#pragma unroll
        for (int nt = 0; nt < 8; nt++) {
            *(uint2*)(ob + nt * 8 + 2 * tg) =
                make_uint2(f2tf(O[mt][nt][0] * inv0), f2tf(O[mt][nt][1] * inv0));
            *(uint2*)(ob + (size_t)8 * ND + nt * 8 + 2 * tg) =
                make_uint2(f2tf(O[mt][nt][2] * inv1), f2tf(O[mt][nt][3] * inv1));
        }
    }
}

// ---------------- launch ------------------------------------------------------
extern "C" void kernel_launch(void* const* d_in, const int* in_sizes, int n_in,
                              void* d_out, int out_size) {
    const float* x  = (const float*)d_in[0];
    const float* Wq = (const float*)d_in[1];
    const float* Wk = (const float*)d_in[2];
    const float* Wv = (const float*)d_in[3];
    const float* Wo = (const float*)d_in[4];
    float* out = (float*)d_out;

    float *q, *k, *v, *o, *xt, *wqt, *wkt, *wvt, *wot;
    cudaGetSymbolAddress((void**)&q, g_q);
    cudaGetSymbolAddress((void**)&k, g_k);
    cudaGetSymbolAddress((void**)&v, g_v);
    cudaGetSymbolAddress((void**)&o, g_o);
    cudaGetSymbolAddress((void**)&xt, g_xt);
    cudaGetSymbolAddress((void**)&wqt, g_wqt);
    cudaGetSymbolAddress((void**)&wkt, g_wkt);
    cudaGetSymbolAddress((void**)&wvt, g_wvt);
    cudaGetSymbolAddress((void**)&wot, g_wot);

    const int gsmem = GSW * sizeof(uint32_t);          // 56832 B
    const int smem_attn = SM_TOT * sizeof(uint32_t);   // 106496 B
    cudaFuncSetAttribute(tgemm<true>, cudaFuncAttributeMaxDynamicSharedMemorySize, gsmem);
    cudaFuncSetAttribute(tgemm<false>, cudaFuncAttributeMaxDynamicSharedMemorySize, gsmem);
    cudaFuncSetAttribute(tgemm_dual, cudaFuncAttributeMaxDynamicSharedMemorySize, gsmem);
    cudaFuncSetAttribute(attn_mma, cudaFuncAttributeMaxDynamicSharedMemorySize, smem_attn);

    // single merged pre-round pass
    round_all<<<(RN4 + 255) / 256, 256>>>(x, xt, Wq, wqt, Wk, wkt, Wv, wvt, Wo, wot);

    // projections (outputs rounded to tf32 bits)
    tgemm<true><<<dim3(ND / 128, MTOT / 128), 128, gsmem>>>(xt, wqt, q, MTOT, ND, ND);
    tgemm_dual<<<dim3(256 / 128, MTOT / 128, 2), 128, gsmem>>>(xt, wkt, wvt, k, v, MTOT, 256, ND);

    attn_mma<<<dim3(NS / 128, NH, NB), 128, smem_attn>>>();

    // output projection (exact fp32 store)
    tgemm<false><<<dim3(ND / 128, MTOT / 128), 128, gsmem>>>(o, wot, out, MTOT, ND, ND);
}

// round 9
// speedup vs baseline: 2.0771x; 1.8468x over previous
#include <cuda_runtime.h>
#include <cuda_fp16.h>
#include <math.h>
#include <cstdint>

#define NB 4
#define NS 2048
#define ND 1024
#define NH 16
#define NKV 4
#define NHD 64
#define MTOT (NB * NS)   // 8192

// ---------------- scratch (static device globals; no allocation) -------------
__device__ __half g_xh[(size_t)MTOT * ND];
__device__ __half g_qh[(size_t)MTOT * ND];
__device__ __half g_kh[(size_t)MTOT * 256];
__device__ __half g_vh[(size_t)MTOT * 256];
__device__ __half g_oh[(size_t)MTOT * ND];
__device__ __half g_wqh[(size_t)ND * ND];
__device__ __half g_wkh[(size_t)ND * 256];
__device__ __half g_wvh[(size_t)ND * 256];
__device__ __half g_woh[(size_t)ND * ND];

// ---------------- helpers -----------------------------------------------------
__device__ __forceinline__ float ex2(float x) {
    float y;
    asm("ex2.approx.f32 %0, %1;" : "=f"(y) : "f"(x));
    return y;
}
__device__ __forceinline__ uint32_t smem_u32(const void* p) {
    uint32_t a;
    asm("{ .reg .u64 t; cvta.to.shared.u64 t, %1; cvt.u32.u64 %0, t; }" : "=r"(a) : "l"(p));
    return a;
}
__device__ __forceinline__ uint32_t packh2(float lo, float hi) {
    __half2 h = __floats2half2_rn(lo, hi);
    return *reinterpret_cast<uint32_t*>(&h);
}
__device__ __forceinline__ void ldmx4(uint32_t* r, uint32_t addr) {
    asm volatile("ldmatrix.sync.aligned.m8n8.x4.shared.b16 {%0,%1,%2,%3}, [%4];"
                 : "=r"(r[0]), "=r"(r[1]), "=r"(r[2]), "=r"(r[3]) : "r"(addr));
}
__device__ __forceinline__ void ldmx4t(uint32_t* r, uint32_t addr) {
    asm volatile("ldmatrix.sync.aligned.m8n8.x4.trans.shared.b16 {%0,%1,%2,%3}, [%4];"
                 : "=r"(r[0]), "=r"(r[1]), "=r"(r[2]), "=r"(r[3]) : "r"(addr));
}
__device__ __forceinline__ void cpa16(uint32_t dst, const void* src) {
    asm volatile("cp.async.ca.shared.global [%0], [%1], 16;" :: "r"(dst), "l"(src));
}
__device__ __forceinline__ void cpa_commit() {
    asm volatile("cp.async.commit_group;" ::: "memory");
}
__device__ __forceinline__ void cpa_wait0() {
    asm volatile("cp.async.wait_group 0;" ::: "memory");
}
__device__ __forceinline__ void cpa_wait1() {
    asm volatile("cp.async.wait_group 1;" ::: "memory");
}
// D += A(16x16) * B(16x8), fp16 inputs, fp32 accum.
__device__ __forceinline__ void mma16(float* c, const uint32_t* a, uint32_t b0, uint32_t b1) {
    asm volatile(
        "mma.sync.aligned.m16n8k16.row.col.f32.f16.f16.f32 "
        "{%0,%1,%2,%3}, {%4,%5,%6,%7}, {%8,%9}, {%0,%1,%2,%3};"
        : "+f"(c[0]), "+f"(c[1]), "+f"(c[2]), "+f"(c[3])
        : "r"(a[0]), "r"(a[1]), "r"(a[2]), "r"(a[3]), "r"(b0), "r"(b1));
}

// ---------------- merged fp32->fp16 convert kernel ---------------------------
#define RN0 (MTOT * ND / 4)
#define RN1 (RN0 + ND * ND / 4)
#define RN2 (RN1 + ND * 256 / 4)
#define RN3 (RN2 + ND * 256 / 4)
#define RN4 (RN3 + ND * ND / 4)

__global__ __launch_bounds__(256) void cvt_all(
    const float* __restrict__ x,  __half* __restrict__ xh,
    const float* __restrict__ wq, __half* __restrict__ wqh,
    const float* __restrict__ wk, __half* __restrict__ wkh,
    const float* __restrict__ wv, __half* __restrict__ wvh,
    const float* __restrict__ wo, __half* __restrict__ woh) {
    int i = blockIdx.x * 256 + threadIdx.x;
    const float* s; __half* d; int j;
    if (i < RN0)      { s = x;  d = xh;  j = i; }
    else if (i < RN1) { s = wq; d = wqh; j = i - RN0; }
    else if (i < RN2) { s = wk; d = wkh; j = i - RN1; }
    else if (i < RN3) { s = wv; d = wvh; j = i - RN2; }
    else if (i < RN4) { s = wo; d = woh; j = i - RN3; }
    else return;
    float4 v = ((const float4*)s)[j];
    ((uint2*)d)[j] = make_uint2(packh2(v.x, v.y), packh2(v.z, v.w));
}

// ---------------- fp16 GEMM: C = A[M,K] @ W[K,N], 3-stage cp.async -----------
// 128 thr (4 warps 2x2), tile 128x128x32, warp tile 64x64.
#define APH 20                        // A pitch in words (40 fp16)
#define WPH 68                        // W pitch in words (136 fp16)
#define ABUFW (128 * APH)             // 2560 words
#define WBUFW (32 * WPH)              // 2176 words
#define GSW (3 * (ABUFW + WBUFW))     // 14208 words = 56832 B

template <bool H16OUT>
__device__ __forceinline__ void tgemm_body(const __half* __restrict__ A,
                                           const __half* __restrict__ W,
                                           void* __restrict__ Cv,
                                           int M, int N, int K, uint32_t* sm) {
    const int tid = threadIdx.x, wid = tid >> 5, lane = tid & 31;
    const int g = lane >> 2, tg = lane & 3;
    const int bm = blockIdx.y, bn = blockIdx.x;
    const int wm = wid >> 1, wn = wid & 1;
    const int rowsel = lane & 15, colsel = lane >> 4;

    const uint32_t smb = smem_u32(sm);
    const uint32_t ws0 = 3 * ABUFW;

    const __half* Ap = A + (size_t)(bm * 128 + tid) * K;
    const int wrow = tid >> 4, wseg = tid & 15;
    const __half* Wp = W + (size_t)wrow * N + bn * 128 + wseg * 8;

    const int nk = K / 32;

    auto load_tile = [&](int kt, int buf) {
        const uint32_t ab = smb + (uint32_t)(buf * ABUFW) * 4;
        const uint32_t wb = smb + (uint32_t)(ws0 + buf * WBUFW) * 4;
        const __half* ap = Ap + kt * 32;
#pragma unroll
        for (int s = 0; s < 4; s++)
            cpa16(ab + (uint32_t)(tid * APH + s * 4) * 4, ap + s * 8);
        const __half* wp = Wp + (size_t)kt * 32 * N;
#pragma unroll
        for (int r = 0; r < 4; r++)
            cpa16(wb + (uint32_t)((wrow + r * 8) * WPH + wseg * 4) * 4,
                  wp + (size_t)r * 8 * N);
        cpa_commit();
    };

    float acc[4][8][4];
#pragma unroll
    for (int i = 0; i < 4; i++)
#pragma unroll
        for (int j = 0; j < 8; j++)
#pragma unroll
            for (int r = 0; r < 4; r++) acc[i][j][r] = 0.f;

    load_tile(0, 0);
    load_tile(1, 1);

    int cur = 0;
    for (int kt = 0; kt < nk; kt++) {
        if (kt + 1 < nk) cpa_wait1(); else cpa_wait0();
        __syncthreads();
        int pre = cur + 2; if (pre >= 3) pre -= 3;
        if (kt + 2 < nk) load_tile(kt + 2, pre);

        const uint32_t ab = smb + (uint32_t)(cur * ABUFW) * 4;
        const uint32_t wb = smb + (uint32_t)(ws0 + cur * WBUFW) * 4;
#pragma unroll
        for (int ks = 0; ks < 2; ks++) {
            uint32_t a[4][4];
#pragma unroll
            for (int mt = 0; mt < 4; mt++)
                ldmx4(a[mt], ab + (uint32_t)((wm * 64 + mt * 16 + rowsel) * APH +
                                             ks * 8 + colsel * 4) * 4);
#pragma unroll
            for (int np = 0; np < 4; np++) {
                uint32_t r4[4];
                ldmx4t(r4, wb + (uint32_t)((ks * 16 + rowsel) * WPH +
                                           wn * 32 + np * 8 + colsel * 4) * 4);
#pragma unroll
                for (int mt = 0; mt < 4; mt++) {
                    mma16(acc[mt][2 * np],     a[mt], r4[0], r4[1]);
                    mma16(acc[mt][2 * np + 1], a[mt], r4[2], r4[3]);
                }
            }
        }
        if (++cur == 3) cur = 0;
    }

#pragma unroll
    for (int mt = 0; mt < 4; mt++)
#pragma unroll
        for (int nt = 0; nt < 8; nt++) {
            int row = bm * 128 + wm * 64 + mt * 16 + g;
            int col = bn * 128 + wn * 64 + nt * 8 + 2 * tg;
            if (H16OUT) {
                uint32_t* C = (uint32_t*)Cv;
                C[((size_t)row * N + col) >> 1] = packh2(acc[mt][nt][0], acc[mt][nt][1]);
                C[((size_t)(row + 8) * N + col) >> 1] = packh2(acc[mt][nt][2], acc[mt][nt][3]);
            } else {
                float* C = (float*)Cv;
                *(float2*)(C + (size_t)row * N + col) =
                    make_float2(acc[mt][nt][0], acc[mt][nt][1]);
                *(float2*)(C + (size_t)(row + 8) * N + col) =
                    make_float2(acc[mt][nt][2], acc[mt][nt][3]);
            }
        }
}

template <bool H16OUT>
__global__ void __launch_bounds__(128, 3) tgemm(const __half* __restrict__ A,
                                                const __half* __restrict__ W,
                                                void* __restrict__ C,
                                                int M, int N, int K) {
    extern __shared__ uint32_t smg[];
    tgemm_body<H16OUT>(A, W, C, M, N, K, smg);
}

__global__ void __launch_bounds__(128, 3) tgemm_dual(const __half* __restrict__ A,
                                                     const __half* __restrict__ W0,
                                                     const __half* __restrict__ W1,
                                                     __half* __restrict__ C0,
                                                     __half* __restrict__ C1,
                                                     int M, int N, int K) {
    extern __shared__ uint32_t smg[];
    const __half* W = blockIdx.z ? W1 : W0;
    __half* C = blockIdx.z ? C1 : C0;
    tgemm_body<true>(A, W, C, M, N, K, smg);
}

// ---------------- Flash attention, fp16 mma, P in registers ------------------
// Block 128 thr (4 warps); q-tile 128 (32 rows/warp); kv chunks of 64.
// smem (u32 words): Q stage 128x36, K 2x64x36, V 2x64x36 = 13824 w = 55296 B.
#define HP 36                           // pitch in words (72 fp16)
#define SM_Q 0
#define KBUF (64 * HP)                  // 2304 w
#define SM_K (128 * HP)                 // 4608
#define SM_V (SM_K + 2 * KBUF)          // 9216
#define SM_TOT (SM_V + 2 * KBUF)        // 13824 words

__global__ void __launch_bounds__(128, 2) attn_mma() {
    extern __shared__ uint32_t sm4[];
    const uint32_t smb = smem_u32(sm4);

    const int qb = blockIdx.x, h = blockIdx.y, b = blockIdx.z;
    const int kvh = h >> 2;
    const int tid = threadIdx.x, w = tid >> 5, lane = tid & 31;
    const int g = lane >> 2, tg = lane & 3;
    const int rowsel = lane & 15, colsel = lane >> 4;

    const float LOG2E = 1.4426950408889634f;
    const float sc2 = 0.125f * LOG2E;
    const float slope2 = ex2(-0.5f * (float)(h + 1)) * LOG2E;

    const int lr = tid >> 3;            // loader row within 16-row group
    const int lseg = tid & 7;           // 16B segment within 64-fp16 row

    const __half* kbase = g_kh + (size_t)(b * NS) * 256 + kvh * NHD;
    const __half* vbase = g_vh + (size_t)(b * NS) * 256 + kvh * NHD;

    auto issue_kv = [&](int kt, int buf) {
        const __half* kp = kbase + (size_t)kt * 64 * 256;
        const __half* vp = vbase + (size_t)kt * 64 * 256;
        const uint32_t kd = smb + (uint32_t)(SM_K + buf * KBUF) * 4;
        const uint32_t vd = smb + (uint32_t)(SM_V + buf * KBUF) * 4;
#pragma unroll
        for (int rep = 0; rep < 4; rep++) {
            int r = rep * 16 + lr;
            cpa16(kd + (uint32_t)(r * HP + lseg * 4) * 4, kp + (size_t)r * 256 + lseg * 8);
            cpa16(vd + (uint32_t)(r * HP + lseg * 4) * 4, vp + (size_t)r * 256 + lseg * 8);
        }
        cpa_commit();
    };

    // prologue: K/V chunk 0 + Q tile in flight
    issue_kv(0, 0);
    {
        const __half* qbase = g_qh + (size_t)(b * NS + qb * 128) * ND + h * NHD;
#pragma unroll
        for (int rep = 0; rep < 8; rep++) {
            int r = rep * 16 + lr;
            cpa16(smb + (uint32_t)(SM_Q + r * HP + lseg * 4) * 4,
                  qbase + (size_t)r * ND + lseg * 8);
        }
        cpa_commit();
    }
    cpa_wait0();
    __syncthreads();

    // Q fragments -> registers
    uint32_t qf[4][2][4];
#pragma unroll
    for (int ks = 0; ks < 4; ks++)
#pragma unroll
        for (int mt = 0; mt < 2; mt++)
            ldmx4(qf[ks][mt], smb + (uint32_t)(SM_Q +
                    (w * 32 + mt * 16 + rowsel) * HP + ks * 8 + colsel * 4) * 4);

    float m[4], l[4], O[2][8][4];
#pragma unroll
    for (int i = 0; i < 4; i++) { m[i] = -INFINITY; l[i] = 0.f; }
#pragma unroll
    for (int mt = 0; mt < 2; mt++)
#pragma unroll
        for (int nt = 0; nt < 8; nt++)
#pragma unroll
            for (int r = 0; r < 4; r++) O[mt][nt][r] = 0.f;

    float rowi[4];
#pragma unroll
    for (int mt = 0; mt < 2; mt++) {
        rowi[2 * mt]     = (float)(qb * 128 + w * 32 + mt * 16 + g);
        rowi[2 * mt + 1] = rowi[2 * mt] + 8.f;
    }

    const int NCH = NS / 64;
    for (int kt = 0; kt < NCH; kt++) {
        const int kb = kt & 1;
        if (kt + 1 < NCH) issue_kv(kt + 1, kb ^ 1);

        const uint32_t kcur = smb + (uint32_t)(SM_K + kb * KBUF) * 4;
        const uint32_t vcur = smb + (uint32_t)(SM_V + kb * KBUF) * 4;

        // S = Q K^T  (both m-tiles share each K fragment)
        float S[2][8][4];
#pragma unroll
        for (int mt = 0; mt < 2; mt++)
#pragma unroll
            for (int nt = 0; nt < 8; nt++)
#pragma unroll
                for (int r = 0; r < 4; r++) S[mt][nt][r] = 0.f;

#pragma unroll
        for (int ks = 0; ks < 4; ks++) {
#pragma unroll
            for (int np = 0; np < 4; np++) {
                uint32_t r4[4];
                ldmx4(r4, kcur + (uint32_t)((np * 16 + rowsel) * HP +
                                            ks * 8 + colsel * 4) * 4);
                // non-trans pairing: {r0,r2} -> nt=2np, {r1,r3} -> nt=2np+1
                mma16(S[0][2 * np],     qf[ks][0], r4[0], r4[2]);
                mma16(S[0][2 * np + 1], qf[ks][0], r4[1], r4[3]);
                mma16(S[1][2 * np],     qf[ks][1], r4[0], r4[2]);
                mma16(S[1][2 * np + 1], qf[ks][1], r4[1], r4[3]);
            }
        }

        // softmax (log2 domain) + pack P into A-fragments
        uint32_t ph[2][4][4];
#pragma unroll
        for (int mt = 0; mt < 2; mt++) {
            float mx0 = -INFINITY, mx1 = -INFINITY;
#pragma unroll
            for (int nt = 0; nt < 8; nt++) {
                float j0 = (float)(kt * 64 + nt * 8 + 2 * tg);
                S[mt][nt][0] = S[mt][nt][0] * sc2 + slope2 * (j0 - rowi[2 * mt]);
                S[mt][nt][1] = S[mt][nt][1] * sc2 + slope2 * (j0 + 1.f - rowi[2 * mt]);
                S[mt][nt][2] = S[mt][nt][2] * sc2 + slope2 * (j0 - rowi[2 * mt + 1]);
                S[mt][nt][3] = S[mt][nt][3] * sc2 + slope2 * (j0 + 1.f - rowi[2 * mt + 1]);
                mx0 = fmaxf(mx0, fmaxf(S[mt][nt][0], S[mt][nt][1]));
                mx1 = fmaxf(mx1, fmaxf(S[mt][nt][2], S[mt][nt][3]));
            }
            mx0 = fmaxf(mx0, __shfl_xor_sync(0xffffffffu, mx0, 1));
            mx0 = fmaxf(mx0, __shfl_xor_sync(0xffffffffu, mx0, 2));
            mx1 = fmaxf(mx1, __shfl_xor_sync(0xffffffffu, mx1, 1));
            mx1 = fmaxf(mx1, __shfl_xor_sync(0xffffffffu, mx1, 2));

            float mn0 = fmaxf(m[2 * mt], mx0), mn1 = fmaxf(m[2 * mt + 1], mx1);
            float f0 = ex2(m[2 * mt] - mn0), f1 = ex2(m[2 * mt + 1] - mn1);
            m[2 * mt] = mn0; m[2 * mt + 1] = mn1;

            float rs0 = 0.f, rs1 = 0.f;
#pragma unroll
            for (int nt = 0; nt < 8; nt++) {
                S[mt][nt][0] = ex2(S[mt][nt][0] - mn0);
                S[mt][nt][1] = ex2(S[mt][nt][1] - mn0);
                S[mt][nt][2] = ex2(S[mt][nt][2] - mn1);
                S[mt][nt][3] = ex2(S[mt][nt][3] - mn1);
                rs0 += S[mt][nt][0] + S[mt][nt][1];
                rs1 += S[mt][nt][2] + S[mt][nt][3];
            }
            rs0 += __shfl_xor_sync(0xffffffffu, rs0, 1);
            rs0 += __shfl_xor_sync(0xffffffffu, rs0, 2);
            rs1 += __shfl_xor_sync(0xffffffffu, rs1, 1);
            rs1 += __shfl_xor_sync(0xffffffffu, rs1, 2);
            l[2 * mt] = l[2 * mt] * f0 + rs0;
            l[2 * mt + 1] = l[2 * mt + 1] * f1 + rs1;

#pragma unroll
            for (int nt = 0; nt < 8; nt++) {
                O[mt][nt][0] *= f0; O[mt][nt][1] *= f0;
                O[mt][nt][2] *= f1; O[mt][nt][3] *= f1;
            }

            // C-frag -> A-frag register pack (no smem round trip)
#pragma unroll
            for (int ks = 0; ks < 4; ks++) {
                ph[mt][ks][0] = packh2(S[mt][2 * ks][0], S[mt][2 * ks][1]);
                ph[mt][ks][1] = packh2(S[mt][2 * ks][2], S[mt][2 * ks][3]);
                ph[mt][ks][2] = packh2(S[mt][2 * ks + 1][0], S[mt][2 * ks + 1][1]);
                ph[mt][ks][3] = packh2(S[mt][2 * ks + 1][2], S[mt][2 * ks + 1][3]);
            }
        }

        // O += P @ V
#pragma unroll
        for (int ks = 0; ks < 4; ks++) {
#pragma unroll
            for (int np = 0; np < 4; np++) {
                uint32_t r4[4];
                ldmx4t(r4, vcur + (uint32_t)((ks * 16 + rowsel) * HP +
                                             np * 8 + colsel * 4) * 4);
                // trans pairing: {r0,r1} -> nt=2np, {r2,r3} -> nt=2np+1
                mma16(O[0][2 * np],     ph[0][ks], r4[0], r4[1]);
                mma16(O[0][2 * np + 1], ph[0][ks], r4[2], r4[3]);
                mma16(O[1][2 * np],     ph[1][ks], r4[0], r4[1]);
                mma16(O[1][2 * np + 1], ph[1][ks], r4[2], r4[3]);
            }
        }

        if (kt + 1 < NCH) {
            cpa_wait0();       // next chunk landed (overlapped with compute)
            __syncthreads();   // everyone done with current buffers
        }
    }

    // epilogue: normalize, pack fp16, store (feeds Wo GEMM)
#pragma unroll
    for (int mt = 0; mt < 2; mt++) {
        float inv0 = 1.f / l[2 * mt], inv1 = 1.f / l[2 * mt + 1];
        int rL = b * NS + qb * 128 + w * 32 + mt * 16 + g;
        uint32_t* ob = (uint32_t*)g_oh;
#pragma unroll
        for (int nt = 0; nt < 8; nt++) {
            int col = h * NHD + nt * 8 + 2 * tg;
            ob[((size_t)rL * ND + col) >> 1] =
                packh2(O[mt][nt][0] * inv0, O[mt][nt][1] * inv0);
            ob[((size_t)(rL + 8) * ND + col) >> 1] =
                packh2(O[mt][nt][2] * inv1, O[mt][nt][3] * inv1);
        }
    }
}

// ---------------- launch ------------------------------------------------------
extern "C" void kernel_launch(void* const* d_in, const int* in_sizes, int n_in,
                              void* d_out, int out_size) {
    const float* x  = (const float*)d_in[0];
    const float* Wq = (const float*)d_in[1];
    const float* Wk = (const float*)d_in[2];
    const float* Wv = (const float*)d_in[3];
    const float* Wo = (const float*)d_in[4];
    float* out = (float*)d_out;

    __half *xh, *qh, *kh, *vh, *oh, *wqh, *wkh, *wvh, *woh;
    cudaGetSymbolAddress((void**)&xh, g_xh);
    cudaGetSymbolAddress((void**)&qh, g_qh);
    cudaGetSymbolAddress((void**)&kh, g_kh);
    cudaGetSymbolAddress((void**)&vh, g_vh);
    cudaGetSymbolAddress((void**)&oh, g_oh);
    cudaGetSymbolAddress((void**)&wqh, g_wqh);
    cudaGetSymbolAddress((void**)&wkh, g_wkh);
    cudaGetSymbolAddress((void**)&wvh, g_wvh);
    cudaGetSymbolAddress((void**)&woh, g_woh);

    const int gsmem = GSW * sizeof(uint32_t);          // 56832 B
    const int smem_attn = SM_TOT * sizeof(uint32_t);   // 55296 B
    cudaFuncSetAttribute(tgemm<true>, cudaFuncAttributeMaxDynamicSharedMemorySize, gsmem);
    cudaFuncSetAttribute(tgemm<false>, cudaFuncAttributeMaxDynamicSharedMemorySize, gsmem);
    cudaFuncSetAttribute(tgemm_dual, cudaFuncAttributeMaxDynamicSharedMemorySize, gsmem);
    cudaFuncSetAttribute(attn_mma, cudaFuncAttributeMaxDynamicSharedMemorySize, smem_attn);

    // one-shot fp32 -> fp16 conversion of x and all weights
    cvt_all<<<(RN4 + 255) / 256, 256>>>(x, xh, Wq, wqh, Wk, wkh, Wv, wvh, Wo, woh);

    // projections (fp16 in, fp16 out)
    tgemm<true><<<dim3(ND / 128, MTOT / 128), 128, gsmem>>>(xh, wqh, qh, MTOT, ND, ND);
    tgemm_dual<<<dim3(256 / 128, MTOT / 128, 2), 128, gsmem>>>(xh, wkh, wvh, kh, vh, MTOT, 256, ND);

    attn_mma<<<dim3(NS / 128, NH, NB), 128, smem_attn>>>();

    // output projection (fp16 in, fp32 out)
    tgemm<false><<<dim3(ND / 128, MTOT / 128), 128, gsmem>>>(oh, woh, out, MTOT, ND, ND);
}

// round 10
// speedup vs baseline: 2.3604x; 1.1364x over previous
#include <cuda_runtime.h>
#include <cuda_fp16.h>
#include <math.h>
#include <cstdint>

#define NB 4
#define NS 2048
#define ND 1024
#define NH 16
#define NKV 4
#define NHD 64
#define MTOT (NB * NS)   // 8192

// ---------------- scratch (static device globals; no allocation) -------------
__device__ __half g_xh[(size_t)MTOT * ND];
__device__ __half g_qh[(size_t)MTOT * ND];
__device__ __half g_kh[(size_t)MTOT * 256];
__device__ __half g_vh[(size_t)MTOT * 256];
__device__ __half g_oh[(size_t)MTOT * ND];
__device__ __half g_wqh[(size_t)ND * ND];
__device__ __half g_wkh[(size_t)ND * 256];
__device__ __half g_wvh[(size_t)ND * 256];
__device__ __half g_woh[(size_t)ND * ND];

// ---------------- helpers -----------------------------------------------------
__device__ __forceinline__ float ex2(float x) {
    float y;
    asm("ex2.approx.f32 %0, %1;" : "=f"(y) : "f"(x));
    return y;
}
__device__ __forceinline__ uint32_t smem_u32(const void* p) {
    uint32_t a;
    asm("{ .reg .u64 t; cvta.to.shared.u64 t, %1; cvt.u32.u64 %0, t; }" : "=r"(a) : "l"(p));
    return a;
}
__device__ __forceinline__ uint32_t packh2(float lo, float hi) {
    __half2 h = __floats2half2_rn(lo, hi);
    return *reinterpret_cast<uint32_t*>(&h);
}
__device__ __forceinline__ void ldmx4(uint32_t* r, uint32_t addr) {
    asm volatile("ldmatrix.sync.aligned.m8n8.x4.shared.b16 {%0,%1,%2,%3}, [%4];"
                 : "=r"(r[0]), "=r"(r[1]), "=r"(r[2]), "=r"(r[3]) : "r"(addr));
}
__device__ __forceinline__ void ldmx4t(uint32_t* r, uint32_t addr) {
    asm volatile("ldmatrix.sync.aligned.m8n8.x4.trans.shared.b16 {%0,%1,%2,%3}, [%4];"
                 : "=r"(r[0]), "=r"(r[1]), "=r"(r[2]), "=r"(r[3]) : "r"(addr));
}
__device__ __forceinline__ void cpa16(uint32_t dst, const void* src) {
    asm volatile("cp.async.ca.shared.global [%0], [%1], 16;" :: "r"(dst), "l"(src));
}
__device__ __forceinline__ void cpa_commit() {
    asm volatile("cp.async.commit_group;" ::: "memory");
}
__device__ __forceinline__ void cpa_wait0() {
    asm volatile("cp.async.wait_group 0;" ::: "memory");
}
__device__ __forceinline__ void cpa_wait1() {
    asm volatile("cp.async.wait_group 1;" ::: "memory");
}
__device__ __forceinline__ void mma16(float* c, const uint32_t* a, uint32_t b0, uint32_t b1) {
    asm volatile(
        "mma.sync.aligned.m16n8k16.row.col.f32.f16.f16.f32 "
        "{%0,%1,%2,%3}, {%4,%5,%6,%7}, {%8,%9}, {%0,%1,%2,%3};"
        : "+f"(c[0]), "+f"(c[1]), "+f"(c[2]), "+f"(c[3])
        : "r"(a[0]), "r"(a[1]), "r"(a[2]), "r"(a[3]), "r"(b0), "r"(b1));
}

// ---------------- merged fp32->fp16 convert kernel ---------------------------
#define RN0 (MTOT * ND / 4)
#define RN1 (RN0 + ND * ND / 4)
#define RN2 (RN1 + ND * 256 / 4)
#define RN3 (RN2 + ND * 256 / 4)
#define RN4 (RN3 + ND * ND / 4)

__global__ __launch_bounds__(256) void cvt_all(
    const float* __restrict__ x,  __half* __restrict__ xh,
    const float* __restrict__ wq, __half* __restrict__ wqh,
    const float* __restrict__ wk, __half* __restrict__ wkh,
    const float* __restrict__ wv, __half* __restrict__ wvh,
    const float* __restrict__ wo, __half* __restrict__ woh) {
    int i = blockIdx.x * 256 + threadIdx.x;
    const float* s; __half* d; int j;
    if (i < RN0)      { s = x;  d = xh;  j = i; }
    else if (i < RN1) { s = wq; d = wqh; j = i - RN0; }
    else if (i < RN2) { s = wk; d = wkh; j = i - RN1; }
    else if (i < RN3) { s = wv; d = wvh; j = i - RN2; }
    else if (i < RN4) { s = wo; d = woh; j = i - RN3; }
    else return;
    float4 v = ((const float4*)s)[j];
    ((uint2*)d)[j] = make_uint2(packh2(v.x, v.y), packh2(v.z, v.w));
}

// ---------------- fp16 GEMM body: C = A[M,K] @ W[K,N], 3-stage cp.async ------
#define APH 20
#define WPH 68
#define ABUFW (128 * APH)
#define WBUFW (32 * WPH)
#define GSW (3 * (ABUFW + WBUFW))     // 14208 words = 56832 B

template <bool H16OUT>
__device__ __forceinline__ void tgemm_body(const __half* __restrict__ A,
                                           const __half* __restrict__ W,
                                           void* __restrict__ Cv,
                                           int N, int K, int bn, uint32_t* sm) {
    const int tid = threadIdx.x, wid = tid >> 5, lane = tid & 31;
    const int g = lane >> 2, tg = lane & 3;
    const int bm = blockIdx.y;
    const int wm = wid >> 1, wn = wid & 1;
    const int rowsel = lane & 15, colsel = lane >> 4;

    const uint32_t smb = smem_u32(sm);
    const uint32_t ws0 = 3 * ABUFW;

    const __half* Ap = A + (size_t)(bm * 128 + tid) * K;
    const int wrow = tid >> 4, wseg = tid & 15;
    const __half* Wp = W + (size_t)wrow * N + bn * 128 + wseg * 8;

    const int nk = K / 32;

    auto load_tile = [&](int kt, int buf) {
        const uint32_t ab = smb + (uint32_t)(buf * ABUFW) * 4;
        const uint32_t wb = smb + (uint32_t)(ws0 + buf * WBUFW) * 4;
        const __half* ap = Ap + kt * 32;
#pragma unroll
        for (int s = 0; s < 4; s++)
            cpa16(ab + (uint32_t)(tid * APH + s * 4) * 4, ap + s * 8);
        const __half* wp = Wp + (size_t)kt * 32 * N;
#pragma unroll
        for (int r = 0; r < 4; r++)
            cpa16(wb + (uint32_t)((wrow + r * 8) * WPH + wseg * 4) * 4,
                  wp + (size_t)r * 8 * N);
        cpa_commit();
    };

    float acc[4][8][4];
#pragma unroll
    for (int i = 0; i < 4; i++)
#pragma unroll
        for (int j = 0; j < 8; j++)
#pragma unroll
            for (int r = 0; r < 4; r++) acc[i][j][r] = 0.f;

    load_tile(0, 0);
    load_tile(1, 1);

    int cur = 0;
    for (int kt = 0; kt < nk; kt++) {
        if (kt + 1 < nk) cpa_wait1(); else cpa_wait0();
        __syncthreads();
        int pre = cur + 2; if (pre >= 3) pre -= 3;
        if (kt + 2 < nk) load_tile(kt + 2, pre);

        const uint32_t ab = smb + (uint32_t)(cur * ABUFW) * 4;
        const uint32_t wb = smb + (uint32_t)(ws0 + cur * WBUFW) * 4;
#pragma unroll
        for (int ks = 0; ks < 2; ks++) {
            uint32_t a[4][4];
#pragma unroll
            for (int mt = 0; mt < 4; mt++)
                ldmx4(a[mt], ab + (uint32_t)((wm * 64 + mt * 16 + rowsel) * APH +
                                             ks * 8 + colsel * 4) * 4);
#pragma unroll
            for (int np = 0; np < 4; np++) {
                uint32_t r4[4];
                ldmx4t(r4, wb + (uint32_t)((ks * 16 + rowsel) * WPH +
                                           wn * 32 + np * 8 + colsel * 4) * 4);
#pragma unroll
                for (int mt = 0; mt < 4; mt++) {
                    mma16(acc[mt][2 * np],     a[mt], r4[0], r4[1]);
                    mma16(acc[mt][2 * np + 1], a[mt], r4[2], r4[3]);
                }
            }
        }
        if (++cur == 3) cur = 0;
    }

#pragma unroll
    for (int mt = 0; mt < 4; mt++)
#pragma unroll
        for (int nt = 0; nt < 8; nt++) {
            int row = bm * 128 + wm * 64 + mt * 16 + g;
            int col = bn * 128 + wn * 64 + nt * 8 + 2 * tg;
            if (H16OUT) {
                uint32_t* C = (uint32_t*)Cv;
                C[((size_t)row * N + col) >> 1] = packh2(acc[mt][nt][0], acc[mt][nt][1]);
                C[((size_t)(row + 8) * N + col) >> 1] = packh2(acc[mt][nt][2], acc[mt][nt][3]);
            } else {
                float* C = (float*)Cv;
                *(float2*)(C + (size_t)row * N + col) =
                    make_float2(acc[mt][nt][0], acc[mt][nt][1]);
                *(float2*)(C + (size_t)(row + 8) * N + col) =
                    make_float2(acc[mt][nt][2], acc[mt][nt][3]);
            }
        }
}

// merged QKV projection: grid (12, 64). tiles 0-7 -> Q, 8-9 -> K, 10-11 -> V.
__global__ void __launch_bounds__(128, 3) tgemm_qkv(const __half* __restrict__ A,
                                                    const __half* __restrict__ wq,
                                                    const __half* __restrict__ wk,
                                                    const __half* __restrict__ wv,
                                                    __half* __restrict__ q,
                                                    __half* __restrict__ k,
                                                    __half* __restrict__ v) {
    extern __shared__ uint32_t smg[];
    const int bx = blockIdx.x;
    const __half* W; __half* C; int N, bn;
    if (bx < 8)       { W = wq; C = q; N = ND;  bn = bx; }
    else if (bx < 10) { W = wk; C = k; N = 256; bn = bx - 8; }
    else              { W = wv; C = v; N = 256; bn = bx - 10; }
    tgemm_body<true>(A, W, C, N, ND, bn, smg);
}

__global__ void __launch_bounds__(128, 3) tgemm_wo(const __half* __restrict__ A,
                                                   const __half* __restrict__ W,
                                                   float* __restrict__ C) {
    extern __shared__ uint32_t smg[];
    tgemm_body<false>(A, W, C, ND, ND, blockIdx.x, smg);
}

// ---------------- Flash attention, fp16 mma, static-max softmax --------------
// Softmax shift-invariance: exponent e = s*sc2 + slope2*(j - (S-1)) is
// row-independent and <= s*sc2 (bounded ~3), so single-pass exp/sum with NO
// running max, NO rescaling. Mathematically identical to reference softmax.
#define HP 36
#define SM_Q 0
#define KBUF (64 * HP)
#define SM_K (128 * HP)
#define SM_V (SM_K + 2 * KBUF)
#define SM_TOT (SM_V + 2 * KBUF)        // 13824 words = 55296 B

__global__ void __launch_bounds__(128, 2) attn_mma() {
    extern __shared__ uint32_t sm4[];
    const uint32_t smb = smem_u32(sm4);

    const int qb = blockIdx.x, h = blockIdx.y, b = blockIdx.z;
    const int kvh = h >> 2;
    const int tid = threadIdx.x, w = tid >> 5, lane = tid & 31;
    const int g = lane >> 2, tg = lane & 3;
    const int rowsel = lane & 15, colsel = lane >> 4;

    const float LOG2E = 1.4426950408889634f;
    const float sc2 = 0.125f * LOG2E;
    const float slope2 = ex2(-0.5f * (float)(h + 1)) * LOG2E;

    const int lr = tid >> 3;
    const int lseg = tid & 7;

    const __half* kbase = g_kh + (size_t)(b * NS) * 256 + kvh * NHD;
    const __half* vbase = g_vh + (size_t)(b * NS) * 256 + kvh * NHD;

    auto issue_kv = [&](int kt, int buf) {
        const __half* kp = kbase + (size_t)kt * 64 * 256;
        const __half* vp = vbase + (size_t)kt * 64 * 256;
        const uint32_t kd = smb + (uint32_t)(SM_K + buf * KBUF) * 4;
        const uint32_t vd = smb + (uint32_t)(SM_V + buf * KBUF) * 4;
#pragma unroll
        for (int rep = 0; rep < 4; rep++) {
            int r = rep * 16 + lr;
            cpa16(kd + (uint32_t)(r * HP + lseg * 4) * 4, kp + (size_t)r * 256 + lseg * 8);
            cpa16(vd + (uint32_t)(r * HP + lseg * 4) * 4, vp + (size_t)r * 256 + lseg * 8);
        }
        cpa_commit();
    };

    issue_kv(0, 0);
    {
        const __half* qbase = g_qh + (size_t)(b * NS + qb * 128) * ND + h * NHD;
#pragma unroll
        for (int rep = 0; rep < 8; rep++) {
            int r = rep * 16 + lr;
            cpa16(smb + (uint32_t)(SM_Q + r * HP + lseg * 4) * 4,
                  qbase + (size_t)r * ND + lseg * 8);
        }
        cpa_commit();
    }
    cpa_wait0();
    __syncthreads();

    uint32_t qf[4][2][4];
#pragma unroll
    for (int ks = 0; ks < 4; ks++)
#pragma unroll
        for (int mt = 0; mt < 2; mt++)
            ldmx4(qf[ks][mt], smb + (uint32_t)(SM_Q +
                    (w * 32 + mt * 16 + rowsel) * HP + ks * 8 + colsel * 4) * 4);

    float l[4], O[2][8][4];
#pragma unroll
    for (int i = 0; i < 4; i++) l[i] = 0.f;
#pragma unroll
    for (int mt = 0; mt < 2; mt++)
#pragma unroll
        for (int nt = 0; nt < 8; nt++)
#pragma unroll
            for (int r = 0; r < 4; r++) O[mt][nt][r] = 0.f;

    const int NCH = NS / 64;
    for (int kt = 0; kt < NCH; kt++) {
        const int kb = kt & 1;
        if (kt + 1 < NCH) issue_kv(kt + 1, kb ^ 1);

        const uint32_t kcur = smb + (uint32_t)(SM_K + kb * KBUF) * 4;
        const uint32_t vcur = smb + (uint32_t)(SM_V + kb * KBUF) * 4;

        // S = Q K^T
        float S[2][8][4];
#pragma unroll
        for (int mt = 0; mt < 2; mt++)
#pragma unroll
            for (int nt = 0; nt < 8; nt++)
#pragma unroll
                for (int r = 0; r < 4; r++) S[mt][nt][r] = 0.f;

#pragma unroll
        for (int ks = 0; ks < 4; ks++) {
#pragma unroll
            for (int np = 0; np < 4; np++) {
                uint32_t r4[4];
                ldmx4(r4, kcur + (uint32_t)((np * 16 + rowsel) * HP +
                                            ks * 8 + colsel * 4) * 4);
                mma16(S[0][2 * np],     qf[ks][0], r4[0], r4[2]);
                mma16(S[0][2 * np + 1], qf[ks][0], r4[1], r4[3]);
                mma16(S[1][2 * np],     qf[ks][1], r4[0], r4[2]);
                mma16(S[1][2 * np + 1], qf[ks][1], r4[1], r4[3]);
            }
        }

        // static-max softmax: e = s*sc2 + slope2*(j - (S-1)); p = 2^e
        const float base = slope2 * (float)(kt * 64 + 2 * tg - (NS - 1));
        uint32_t ph[2][4][4];
#pragma unroll
        for (int mt = 0; mt < 2; mt++) {
            float rs0 = 0.f, rs1 = 0.f;
#pragma unroll
            for (int nt = 0; nt < 8; nt++) {
                const float b0 = fmaf((float)(8 * nt), slope2, base);
                const float b1 = b0 + slope2;
                S[mt][nt][0] = ex2(fmaf(S[mt][nt][0], sc2, b0));
                S[mt][nt][1] = ex2(fmaf(S[mt][nt][1], sc2, b1));
                S[mt][nt][2] = ex2(fmaf(S[mt][nt][2], sc2, b0));
                S[mt][nt][3] = ex2(fmaf(S[mt][nt][3], sc2, b1));
                rs0 += S[mt][nt][0] + S[mt][nt][1];
                rs1 += S[mt][nt][2] + S[mt][nt][3];
            }
            rs0 += __shfl_xor_sync(0xffffffffu, rs0, 1);
            rs0 += __shfl_xor_sync(0xffffffffu, rs0, 2);
            rs1 += __shfl_xor_sync(0xffffffffu, rs1, 1);
            rs1 += __shfl_xor_sync(0xffffffffu, rs1, 2);
            l[2 * mt] += rs0;
            l[2 * mt + 1] += rs1;

            // C-frag -> A-frag register pack
#pragma unroll
            for (int ks = 0; ks < 4; ks++) {
                ph[mt][ks][0] = packh2(S[mt][2 * ks][0], S[mt][2 * ks][1]);
                ph[mt][ks][1] = packh2(S[mt][2 * ks][2], S[mt][2 * ks][3]);
                ph[mt][ks][2] = packh2(S[mt][2 * ks + 1][0], S[mt][2 * ks + 1][1]);
                ph[mt][ks][3] = packh2(S[mt][2 * ks + 1][2], S[mt][2 * ks + 1][3]);
            }
        }

        // O += P @ V  (no rescale needed — exponents are globally consistent)
#pragma unroll
        for (int ks = 0; ks < 4; ks++) {
#pragma unroll
            for (int np = 0; np < 4; np++) {
                uint32_t r4[4];
                ldmx4t(r4, vcur + (uint32_t)((ks * 16 + rowsel) * HP +
                                             np * 8 + colsel * 4) * 4);
                mma16(O[0][2 * np],     ph[0][ks], r4[0], r4[1]);
                mma16(O[0][2 * np + 1], ph[0][ks], r4[2], r4[3]);
                mma16(O[1][2 * np],     ph[1][ks], r4[0], r4[1]);
                mma16(O[1][2 * np + 1], ph[1][ks], r4[2], r4[3]);
            }
        }

        if (kt + 1 < NCH) {
            cpa_wait0();
            __syncthreads();
        }
    }

    // epilogue: normalize, pack fp16, store
#pragma unroll
    for (int mt = 0; mt < 2; mt++) {
        float inv0 = 1.f / l[2 * mt], inv1 = 1.f / l[2 * mt + 1];
        int rL = b * NS + qb * 128 + w * 32 + mt * 16 + g;
        uint32_t* ob = (uint32_t*)g_oh;
#pragma unroll
        for (int nt = 0; nt < 8; nt++) {
            int col = h * NHD + nt * 8 + 2 * tg;
            ob[((size_t)rL * ND + col) >> 1] =
                packh2(O[mt][nt][0] * inv0, O[mt][nt][1] * inv0);
            ob[((size_t)(rL + 8) * ND + col) >> 1] =
                packh2(O[mt][nt][2] * inv1, O[mt][nt][3] * inv1);
        }
    }
}

// ---------------- launch ------------------------------------------------------
extern "C" void kernel_launch(void* const* d_in, const int* in_sizes, int n_in,
                              void* d_out, int out_size) {
    const float* x  = (const float*)d_in[0];
    const float* Wq = (const float*)d_in[1];
    const float* Wk = (const float*)d_in[2];
    const float* Wv = (const float*)d_in[3];
    const float* Wo = (const float*)d_in[4];
    float* out = (float*)d_out;

    __half *xh, *qh, *kh, *vh, *oh, *wqh, *wkh, *wvh, *woh;
    cudaGetSymbolAddress((void**)&xh, g_xh);
    cudaGetSymbolAddress((void**)&qh, g_qh);
    cudaGetSymbolAddress((void**)&kh, g_kh);
    cudaGetSymbolAddress((void**)&vh, g_vh);
    cudaGetSymbolAddress((void**)&oh, g_oh);
    cudaGetSymbolAddress((void**)&wqh, g_wqh);
    cudaGetSymbolAddress((void**)&wkh, g_wkh);
    cudaGetSymbolAddress((void**)&wvh, g_wvh);
    cudaGetSymbolAddress((void**)&woh, g_woh);

    const int gsmem = GSW * sizeof(uint32_t);          // 56832 B
    const int smem_attn = SM_TOT * sizeof(uint32_t);   // 55296 B
    cudaFuncSetAttribute(tgemm_qkv, cudaFuncAttributeMaxDynamicSharedMemorySize, gsmem);
    cudaFuncSetAttribute(tgemm_wo, cudaFuncAttributeMaxDynamicSharedMemorySize, gsmem);
    cudaFuncSetAttribute(attn_mma, cudaFuncAttributeMaxDynamicSharedMemorySize, smem_attn);

    cvt_all<<<(RN4 + 255) / 256, 256>>>(x, xh, Wq, wqh, Wk, wkh, Wv, wvh, Wo, woh);

    tgemm_qkv<<<dim3(12, MTOT / 128), 128, gsmem>>>(xh, wqh, wkh, wvh, qh, kh, vh);

    attn_mma<<<dim3(NS / 128, NH, NB), 128, smem_attn>>>();

    tgemm_wo<<<dim3(ND / 128, MTOT / 128), 128, gsmem>>>(oh, woh, out);
}